// round 3
// baseline (speedup 1.0000x reference)
#include <cuda_runtime.h>

// BTT layer: B=4096, M1=M2=N1=N2=64, R=4.
//   stage1: t[b, m2, n1*4+r] = sum_m1 x[b, m2*64+m1] * W1[m2, m1, n1*4+r]
//   stage2: y[b, n1*64+n2]   = sum_{m2,r} t[b, n1, m2*4+r] * W2[n1, m2*4+r, n2]
// Intermediate stored directly in stage-2 layout: g_t[b][n1][m2*4+r].

#define NB      4096
#define DIM     64        // M1 == M2 == N1 == N2
#define RR      4
#define TROW    16384     // 64*256 floats per b-row of g_t
#define XROW    4096

// 268 MB scratch (allowed: __device__ global, no runtime allocation)
__device__ float g_t[(size_t)NB * DIM * DIM * RR];

__device__ __forceinline__ void fma2(unsigned long long &d,
                                     unsigned long long a,
                                     unsigned long long b) {
    asm volatile("fma.rn.f32x2 %0, %1, %2, %0;" : "+l"(d) : "l"(a), "l"(b));
}
__device__ __forceinline__ unsigned long long dup2(float x) {
    unsigned long long r;
    asm("mov.b64 %0, {%1, %1};" : "=l"(r) : "f"(x));
    return r;
}
__device__ __forceinline__ float4 pair_to_f4(unsigned long long a, unsigned long long b) {
    float2 lo = *reinterpret_cast<float2*>(&a);
    float2 hi = *reinterpret_cast<float2*>(&b);
    return make_float4(lo.x, lo.y, hi.x, hi.y);
}

// ---------------------------------------------------------------------------
// Stage 1: for each m2 (blockIdx.y): (4096 x 64) @ (64 x 256)
// Block: 64 b-rows x 256 c-cols, 256 threads, thread tile 8b x 8c.
// SMEM: Ws[64][256] (full W1[m2]), Xs[64][64] (x tile, row-major, no pad:
//       compute loads are warp-broadcast so no bank conflicts).
// ---------------------------------------------------------------------------
#define S1_SMEM ((DIM*256 + DIM*DIM) * 4)   // 81920 B

__global__ void __launch_bounds__(256, 2)
stage1_kernel(const float* __restrict__ x, const float* __restrict__ W1) {
    const int m2 = blockIdx.y;
    const int b0 = blockIdx.x * 64;
    const int tid = threadIdx.x;

    extern __shared__ float smem[];
    float* Ws = smem;               // [64][256]
    float* Xs = smem + DIM * 256;   // [64][64]

    // Load W1[m2] (64x256 floats = 4096 float4), fully coalesced.
    {
        const float4* Wg = reinterpret_cast<const float4*>(W1 + (size_t)m2 * DIM * 256);
        float4* Ws4 = reinterpret_cast<float4*>(Ws);
        #pragma unroll
        for (int i = 0; i < 16; i++) Ws4[tid + 256 * i] = Wg[tid + 256 * i];
    }
    // Load x tile rows b0..b0+63, cols m2*64..+64 (row-major into Xs).
    {
        const int r  = tid >> 4;           // 0..15
        const int c4 = (tid & 15) * 4;     // 0..60
        #pragma unroll
        for (int p = 0; p < 4; p++) {
            const int b = r + 16 * p;
            float4 v = *reinterpret_cast<const float4*>(
                x + (size_t)(b0 + b) * XROW + m2 * DIM + c4);
            *reinterpret_cast<float4*>(Xs + b * DIM + c4) = v;   // conflict-free STS.128
        }
    }
    __syncthreads();

    const int tx = tid & 31;   // c group: c0 = tx*8  (c = n1*4 + r)
    const int ty = tid >> 5;   // b group: rows ty*8..+8  (constant within warp)

    unsigned long long acc[8][4];
    #pragma unroll
    for (int i = 0; i < 8; i++)
        #pragma unroll
        for (int j = 0; j < 4; j++) acc[i][j] = 0ULL;

    #pragma unroll 4
    for (int k = 0; k < DIM; k++) {
        unsigned long long xf[8];
        #pragma unroll
        for (int i = 0; i < 8; i++)
            xf[i] = dup2(Xs[(ty * 8 + i) * DIM + k]);   // warp-broadcast LDS

        const float* wr = Ws + k * 256 + tx * 8;
        float4 w0 = *reinterpret_cast<const float4*>(wr);
        float4 w1 = *reinterpret_cast<const float4*>(wr + 4);
        unsigned long long wf[4];
        wf[0] = *reinterpret_cast<unsigned long long*>(&w0.x);
        wf[1] = *reinterpret_cast<unsigned long long*>(&w0.z);
        wf[2] = *reinterpret_cast<unsigned long long*>(&w1.x);
        wf[3] = *reinterpret_cast<unsigned long long*>(&w1.z);

        #pragma unroll
        for (int i = 0; i < 8; i++) {
            #pragma unroll
            for (int j = 0; j < 4; j++) fma2(acc[i][j], xf[i], wf[j]);
        }
    }

    // Write to g_t[b][n1][m2*4+r]; c0 = tx*8 -> n1 = 2*tx (first 4), 2*tx+1 (next 4).
    const int n1a = tx * 2;
    #pragma unroll
    for (int i = 0; i < 8; i++) {
        const size_t b = (size_t)(b0 + ty * 8 + i);
        float* base = g_t + b * TROW + m2 * RR;
        *reinterpret_cast<float4*>(base + (size_t)n1a * 256)       = pair_to_f4(acc[i][0], acc[i][1]);
        *reinterpret_cast<float4*>(base + (size_t)(n1a + 1) * 256) = pair_to_f4(acc[i][2], acc[i][3]);
    }
}

// ---------------------------------------------------------------------------
// Stage 2: for each n1 (blockIdx.y): (4096 x 256) @ (256 x 64)
// Block: 128 b-rows x 64 n2-cols, 256 threads, thread tile 8b x 4c.
// SMEM: Ws[256][64] (full W2[n1]), Ts[128][65] (k-chunk of t, padded rows so
//       the two per-warp broadcast rows land in different banks).
// ---------------------------------------------------------------------------
#define TS_PAD 65
#define S2_SMEM ((256*DIM + 128*TS_PAD) * 4)   // 98816 B

__global__ void __launch_bounds__(256, 2)
stage2_kernel(const float* __restrict__ W2, float* __restrict__ y) {
    const int n1 = blockIdx.y;
    const int b0 = blockIdx.x * 128;
    const int tid = threadIdx.x;

    extern __shared__ float smem[];
    float* Ws = smem;               // [256][64]
    float* Ts = smem + 256 * DIM;   // [128][65]

    // Load W2[n1] (256x64 floats = 4096 float4), coalesced.
    {
        const float4* Wg = reinterpret_cast<const float4*>(W2 + (size_t)n1 * 256 * DIM);
        float4* Ws4 = reinterpret_cast<float4*>(Ws);
        #pragma unroll
        for (int i = 0; i < 16; i++) Ws4[tid + 256 * i] = Wg[tid + 256 * i];
    }

    const int tx = tid & 15;   // c group: n2 = tx*4..+4
    const int ty = tid >> 4;   // b group: rows ty*8..+8 (2 values per warp)

    unsigned long long acc[8][2];
    #pragma unroll
    for (int i = 0; i < 8; i++) { acc[i][0] = 0ULL; acc[i][1] = 0ULL; }

    for (int kk = 0; kk < 4; kk++) {
        __syncthreads();
        // Load Ts[128][64] chunk: t[b][n1][kk*64 .. +64], coalesced LDG.128,
        // scalar STS into padded rows.
        #pragma unroll
        for (int p = 0; p < 8; p++) {
            const int idx = tid + 256 * p;         // 0..2047 float4 slots
            const int bb  = idx >> 4;              // 0..127
            const int c4  = (idx & 15) * 4;        // 0..60
            float4 v = *reinterpret_cast<const float4*>(
                g_t + (size_t)(b0 + bb) * TROW + n1 * 256 + kk * DIM + c4);
            float* dst = Ts + bb * TS_PAD + c4;
            dst[0] = v.x; dst[1] = v.y; dst[2] = v.z; dst[3] = v.w;
        }
        __syncthreads();

        #pragma unroll 4
        for (int k = 0; k < DIM; k++) {
            const float* wr = Ws + (kk * DIM + k) * DIM + tx * 4;
            float4 w = *reinterpret_cast<const float4*>(wr);
            unsigned long long wf0 = *reinterpret_cast<unsigned long long*>(&w.x);
            unsigned long long wf1 = *reinterpret_cast<unsigned long long*>(&w.z);
            #pragma unroll
            for (int i = 0; i < 8; i++) {
                unsigned long long xf = dup2(Ts[(ty * 8 + i) * TS_PAD + k]);
                fma2(acc[i][0], xf, wf0);
                fma2(acc[i][1], xf, wf1);
            }
        }
    }

    // y[b][n1*64 + n2]
    #pragma unroll
    for (int i = 0; i < 8; i++) {
        const size_t b = (size_t)(b0 + ty * 8 + i);
        *reinterpret_cast<float4*>(y + b * XROW + n1 * DIM + tx * 4) =
            pair_to_f4(acc[i][0], acc[i][1]);
    }
}

extern "C" void kernel_launch(void* const* d_in, const int* in_sizes, int n_in,
                              void* d_out, int out_size) {
    const float* x  = (const float*)d_in[0];
    const float* W1 = (const float*)d_in[1];
    const float* W2 = (const float*)d_in[2];
    float* y = (float*)d_out;

    cudaFuncSetAttribute(stage1_kernel, cudaFuncAttributeMaxDynamicSharedMemorySize, S1_SMEM);
    cudaFuncSetAttribute(stage2_kernel, cudaFuncAttributeMaxDynamicSharedMemorySize, S2_SMEM);

    dim3 g1(NB / 64, DIM);   // (btile, m2)
    stage1_kernel<<<g1, 256, S1_SMEM>>>(x, W1);

    dim3 g2(NB / 128, DIM);  // (btile, n1)
    stage2_kernel<<<g2, 256, S2_SMEM>>>(W2, y);
}

// round 5
// speedup vs baseline: 1.2695x; 1.2695x over previous
#include <cuda_runtime.h>
#include <cuda_bf16.h>
#include <cstdint>

// BTT layer: B=4096, M1=M2=N1=N2=64, R=4.
//   stage1 (per m2): C[4096x256] = x[:, m2*64:+64] @ W1[m2]   (K=64)
//   stage2 (per n1): y[:, n1*64:+64] = t[n1] @ W2[n1]         (K=256)
// Precision: bf16 hi/lo split, 3 passes (hi*hi + hi*lo + lo*hi) -> ~2e-5 rel err.
// Tensor path: mma.sync.aligned.m16n8k16 (baseline compute_103 PTX; tcgen05 is
// rejected by this harness's non-'a' PTX target).
// Intermediate t: packed (hi | lo<<16) u32, layout [n1][b][k], k = m2*4+r.

#define NB 4096

// ---------------- device globals (scratch; no runtime allocation) ----------
__device__ uint4 g_t[16777216];     // 256MB packed intermediate
__device__ uint4 g_w1hi[131072];    // [m2][n=256][k=64] bf16  (2MB)
__device__ uint4 g_w1lo[131072];
__device__ uint4 g_w2hi[131072];    // [n1][n2=64][k=256] bf16 (2MB)
__device__ uint4 g_w2lo[131072];

// ---------------- helpers ---------------------------------------------------
__device__ __forceinline__ uint32_t fsplit_pack(float v) {
    __nv_bfloat16 h = __float2bfloat16(v);
    float rem = v - __bfloat162float(h);
    __nv_bfloat16 l = __float2bfloat16(rem);
    return (uint32_t)__bfloat16_as_ushort(h) | ((uint32_t)__bfloat16_as_ushort(l) << 16);
}

__device__ __forceinline__ void mma16816(float* c, const uint32_t* a, const uint32_t* b) {
    asm volatile("mma.sync.aligned.m16n8k16.row.col.f32.bf16.bf16.f32 "
        "{%0,%1,%2,%3}, {%4,%5,%6,%7}, {%8,%9}, {%0,%1,%2,%3};"
        : "+f"(c[0]), "+f"(c[1]), "+f"(c[2]), "+f"(c[3])
        : "r"(a[0]), "r"(a[1]), "r"(a[2]), "r"(a[3]), "r"(b[0]), "r"(b[1]));
}

// SMEM tile row stride: 72 bf16 = 144 B (word bank = 4*row + kword, conflict-free
// for the m16n8k16 fragment pattern: rows l/4, kwords l%4).
#define RS 144

// ---------------- prep: split weights into [outer][k] bf16 hi/lo ------------
// W1[m2][k=64][n=256] fp32 -> g_w1{hi,lo}[(m2*256+n)*8 + j] (j = k-octet)
__global__ void prep_w1_kernel(const float* __restrict__ W1) {
    const int m2 = blockIdx.x, n = threadIdx.x;
    const float* Wm = W1 + (size_t)m2 * 16384;
    #pragma unroll
    for (int j = 0; j < 8; j++) {
        uint32_t p[8];
        #pragma unroll
        for (int kk = 0; kk < 8; kk++) p[kk] = fsplit_pack(Wm[(8 * j + kk) * 256 + n]);
        const int idx = (m2 * 256 + n) * 8 + j;
        g_w1hi[idx] = make_uint4(__byte_perm(p[0], p[1], 0x5410), __byte_perm(p[2], p[3], 0x5410),
                                 __byte_perm(p[4], p[5], 0x5410), __byte_perm(p[6], p[7], 0x5410));
        g_w1lo[idx] = make_uint4(__byte_perm(p[0], p[1], 0x7632), __byte_perm(p[2], p[3], 0x7632),
                                 __byte_perm(p[4], p[5], 0x7632), __byte_perm(p[6], p[7], 0x7632));
    }
}
// W2[n1][k=256][n2=64] fp32 -> g_w2{hi,lo}[(n1*64+n2)*32 + kq*8 + j]
__global__ void prep_w2_kernel(const float* __restrict__ W2) {
    const int n1 = blockIdx.x, tid = threadIdx.x;
    const int n2 = tid & 63, kq = tid >> 6;
    const float* Wn = W2 + (size_t)n1 * 16384;
    #pragma unroll
    for (int j = 0; j < 8; j++) {
        const int k0 = kq * 64 + j * 8;
        uint32_t p[8];
        #pragma unroll
        for (int kk = 0; kk < 8; kk++) p[kk] = fsplit_pack(Wn[(k0 + kk) * 64 + n2]);
        const int idx = (n1 * 64 + n2) * 32 + kq * 8 + j;
        g_w2hi[idx] = make_uint4(__byte_perm(p[0], p[1], 0x5410), __byte_perm(p[2], p[3], 0x5410),
                                 __byte_perm(p[4], p[5], 0x5410), __byte_perm(p[6], p[7], 0x5410));
        g_w2lo[idx] = make_uint4(__byte_perm(p[0], p[1], 0x7632), __byte_perm(p[2], p[3], 0x7632),
                                 __byte_perm(p[4], p[5], 0x7632), __byte_perm(p[6], p[7], 0x7632));
    }
}

// ---------------- one MMA pass over a 128xN tile, K=64 ----------------------
// A: [128 rows][RS], B: [N rows][RS]. Warp (wr,wc); NT n-tiles of 8.
template <int NT>
__device__ __forceinline__ void mma_pass(const char* A, const char* B,
                                         float acc[2][NT][4],
                                         int wr, int wc, int qr, int qc) {
    #pragma unroll
    for (int ks = 0; ks < 4; ks++) {
        uint32_t a[2][4];
        #pragma unroll
        for (int mt = 0; mt < 2; mt++) {
            const char* p = A + (wr * 32 + mt * 16 + qr) * RS + (ks * 16 + qc * 2) * 2;
            a[mt][0] = *(const uint32_t*)p;
            a[mt][1] = *(const uint32_t*)(p + 8 * RS);
            a[mt][2] = *(const uint32_t*)(p + 16);
            a[mt][3] = *(const uint32_t*)(p + 8 * RS + 16);
        }
        uint32_t b[NT][2];
        #pragma unroll
        for (int nt = 0; nt < NT; nt++) {
            const char* p = B + (wc * NT * 8 + nt * 8 + qr) * RS + (ks * 16 + qc * 2) * 2;
            b[nt][0] = *(const uint32_t*)p;
            b[nt][1] = *(const uint32_t*)(p + 16);
        }
        #pragma unroll
        for (int mt = 0; mt < 2; mt++)
            #pragma unroll
            for (int nt = 0; nt < NT; nt++) mma16816(acc[mt][nt], a[mt], b[nt]);
    }
}

// ---------------- stage 1: block tile 128(b) x 128(n), K=64 -----------------
#define S1_AHI 0
#define S1_ALO 18432
#define S1_BHI 36864
#define S1_BLO 55296
#define S1_SMEM 73728

__global__ void __launch_bounds__(256, 2)
stage1_kernel(const float* __restrict__ x) {
    extern __shared__ char smem[];
    const int tid = threadIdx.x, wid = tid >> 5, lane = tid & 31;
    const int m2 = blockIdx.x, b0 = blockIdx.y * 128, nbase = blockIdx.z * 128;

    // B fill: copy pre-split images (L2-resident), 16B chunks into padded rows.
    {
        const uint4* bh = g_w1hi + (m2 * 256 + nbase) * 8;
        const uint4* bl = g_w1lo + (m2 * 256 + nbase) * 8;
        #pragma unroll
        for (int i = 0; i < 4; i++) {
            const int idx = tid + 256 * i;        // 1024 uint4
            const int row = idx >> 3, q = idx & 7;
            *(uint4*)(smem + S1_BHI + row * RS + q * 16) = bh[idx];
            *(uint4*)(smem + S1_BLO + row * RS + q * 16) = bl[idx];
        }
    }
    // A fill: x tile 128x64 fp32 -> split hi/lo bf16 pairs.
    #pragma unroll
    for (int i = 0; i < 8; i++) {
        const int idx = tid + 256 * i;            // 2048 float4
        const int row = idx >> 4, c4 = (idx & 15) << 2;
        float4 v = *(const float4*)(x + (size_t)(b0 + row) * 4096 + m2 * 64 + c4);
        uint32_t p0 = fsplit_pack(v.x), p1 = fsplit_pack(v.y),
                 p2 = fsplit_pack(v.z), p3 = fsplit_pack(v.w);
        *(uint2*)(smem + S1_AHI + row * RS + c4 * 2) =
            make_uint2(__byte_perm(p0, p1, 0x5410), __byte_perm(p2, p3, 0x5410));
        *(uint2*)(smem + S1_ALO + row * RS + c4 * 2) =
            make_uint2(__byte_perm(p0, p1, 0x7632), __byte_perm(p2, p3, 0x7632));
    }
    __syncthreads();

    const int wr = wid >> 1, wc = wid & 1, qr = lane >> 2, qc = lane & 3;
    float acc[2][8][4];
    #pragma unroll
    for (int mt = 0; mt < 2; mt++)
        #pragma unroll
        for (int nt = 0; nt < 8; nt++)
            #pragma unroll
            for (int r = 0; r < 4; r++) acc[mt][nt][r] = 0.f;

    mma_pass<8>(smem + S1_AHI, smem + S1_BHI, acc, wr, wc, qr, qc);
    mma_pass<8>(smem + S1_AHI, smem + S1_BLO, acc, wr, wc, qr, qc);
    mma_pass<8>(smem + S1_ALO, smem + S1_BHI, acc, wr, wc, qr, qc);

    // epilogue: pack fp32 -> (hi|lo) u32 pairs, scatter to g_t[n1][b][m2*4+r]
    uint2* gt2 = (uint2*)g_t;
    #pragma unroll
    for (int mt = 0; mt < 2; mt++) {
        const size_t row0 = (size_t)(b0 + wr * 32 + mt * 16 + qr);
        #pragma unroll
        for (int nt = 0; nt < 8; nt++) {
            const int cg = nbase + wc * 64 + nt * 8 + qc * 2;   // global n (0..255)
            const size_t base = (size_t)(cg >> 2) * (NB * 256) + m2 * 4 + (cg & 3);
            gt2[(base + row0 * 256) >> 1] =
                make_uint2(fsplit_pack(acc[mt][nt][0]), fsplit_pack(acc[mt][nt][1]));
            gt2[(base + (row0 + 8) * 256) >> 1] =
                make_uint2(fsplit_pack(acc[mt][nt][2]), fsplit_pack(acc[mt][nt][3]));
        }
    }
}

// ---------------- stage 2: block tile 128(b) x 64(n2), K=256 (4 x 64) -------
#define S2_AHI 0
#define S2_ALO 18432
#define S2_BHI 36864                 // [chunk][64][RS] per half (9216 B/chunk)
#define S2_BLO 73728
#define S2_SMEM 110592

__global__ void __launch_bounds__(256, 2)
stage2_kernel(float* __restrict__ y) {
    extern __shared__ char smem[];
    const int tid = threadIdx.x, wid = tid >> 5, lane = tid & 31;
    const int n1 = blockIdx.x, b0 = blockIdx.y * 128;

    // B fill (once): g_w2 [n2][256] -> chunked [chunk][n2][72]
    {
        const uint4* bh = g_w2hi + n1 * 2048;
        const uint4* bl = g_w2lo + n1 * 2048;
        #pragma unroll
        for (int i = 0; i < 8; i++) {
            const int idx = tid + 256 * i;        // 2048 uint4
            const int n2 = idx >> 5, w = idx & 31;
            const int chunk = w >> 3, q = w & 7;
            const int dst = chunk * 9216 + n2 * RS + q * 16;
            *(uint4*)(smem + S2_BHI + dst) = bh[idx];
            *(uint4*)(smem + S2_BLO + dst) = bl[idx];
        }
    }

    const int wr = wid >> 1, wc = wid & 1, qr = lane >> 2, qc = lane & 3;
    float acc[2][4][4];
    #pragma unroll
    for (int mt = 0; mt < 2; mt++)
        #pragma unroll
        for (int nt = 0; nt < 4; nt++)
            #pragma unroll
            for (int r = 0; r < 4; r++) acc[mt][nt][r] = 0.f;

    const uint4* tsrc = g_t + (size_t)n1 * 262144 + (size_t)b0 * 64;

    for (int ch = 0; ch < 4; ch++) {
        if (ch > 0) __syncthreads();              // prev compute done before A overwrite
        // A fill: 128 rows x 64 packed k -> de-interleave hi/lo
        #pragma unroll
        for (int i = 0; i < 8; i++) {
            const int idx = tid + 256 * i;        // 2048 uint4 (4 k each)
            const int row = idx >> 4, c4 = (idx & 15) << 2;
            uint4 t4 = tsrc[(size_t)row * 64 + ch * 16 + (idx & 15)];
            *(uint2*)(smem + S2_AHI + row * RS + c4 * 2) =
                make_uint2(__byte_perm(t4.x, t4.y, 0x5410), __byte_perm(t4.z, t4.w, 0x5410));
            *(uint2*)(smem + S2_ALO + row * RS + c4 * 2) =
                make_uint2(__byte_perm(t4.x, t4.y, 0x7632), __byte_perm(t4.z, t4.w, 0x7632));
        }
        __syncthreads();

        const char* BH = smem + S2_BHI + ch * 9216;
        const char* BL = smem + S2_BLO + ch * 9216;
        mma_pass<4>(smem + S2_AHI, BH, acc, wr, wc, qr, qc);
        mma_pass<4>(smem + S2_AHI, BL, acc, wr, wc, qr, qc);
        mma_pass<4>(smem + S2_ALO, BH, acc, wr, wc, qr, qc);
    }

    // epilogue: y[b][n1*64 + n2]
    #pragma unroll
    for (int mt = 0; mt < 2; mt++) {
        const size_t row0 = (size_t)(b0 + wr * 32 + mt * 16 + qr);
        #pragma unroll
        for (int nt = 0; nt < 4; nt++) {
            const int col = n1 * 64 + wc * 32 + nt * 8 + qc * 2;
            *(float2*)(y + row0 * 4096 + col) =
                make_float2(acc[mt][nt][0], acc[mt][nt][1]);
            *(float2*)(y + (row0 + 8) * 4096 + col) =
                make_float2(acc[mt][nt][2], acc[mt][nt][3]);
        }
    }
}

// ---------------------------------------------------------------------------
extern "C" void kernel_launch(void* const* d_in, const int* in_sizes, int n_in,
                              void* d_out, int out_size) {
    const float* x  = (const float*)d_in[0];
    const float* W1 = (const float*)d_in[1];
    const float* W2 = (const float*)d_in[2];
    float* y = (float*)d_out;

    cudaFuncSetAttribute(stage1_kernel, cudaFuncAttributeMaxDynamicSharedMemorySize, S1_SMEM);
    cudaFuncSetAttribute(stage2_kernel, cudaFuncAttributeMaxDynamicSharedMemorySize, S2_SMEM);

    prep_w1_kernel<<<64, 256>>>(W1);
    prep_w2_kernel<<<64, 256>>>(W2);
    stage1_kernel<<<dim3(64, 32, 2), 256, S1_SMEM>>>(x);  // x = m2 fastest (t sector merge)
    stage2_kernel<<<dim3(64, 32), 256, S2_SMEM>>>(y);
}

// round 6
// speedup vs baseline: 1.5197x; 1.1971x over previous
#include <cuda_runtime.h>
#include <cuda_bf16.h>
#include <cstdint>

// BTT layer: B=4096, M1=M2=N1=N2=64, R=4.
//   stage1 (per m2): C[4096x256] = x[:, m2*64:+64] @ W1[m2]   (K=64)
//   stage2 (per n1): y[:, n1*64:+64] = t[n1] @ W2[n1]         (K=256)
// bf16 hi/lo split, 3 passes -> ~6e-6 rel err. mma.sync.m16n8k16 + ldmatrix.
// Intermediate t: packed (hi|lo) u32, layout [n1][m2][b][r] -> fully coalesced
// writes (stage1) AND reads (stage2).

#define NB 4096

__device__ uint4 g_t[16777216];     // 256MB: uint4 idx = (n1*64+m2)*4096 + b
__device__ uint4 g_w1hi[131072];    // [m2][n=256][k-octet=8] (2MB)
__device__ uint4 g_w1lo[131072];
__device__ uint4 g_w2hi[131072];    // [n1][n2=64][k-octet=32] (2MB)
__device__ uint4 g_w2lo[131072];

__device__ __forceinline__ uint32_t fsplit_pack(float v) {
    __nv_bfloat16 h = __float2bfloat16(v);
    float rem = v - __bfloat162float(h);
    __nv_bfloat16 l = __float2bfloat16(rem);
    return (uint32_t)__bfloat16_as_ushort(h) | ((uint32_t)__bfloat16_as_ushort(l) << 16);
}
__device__ __forceinline__ void mma16816(float* c, const uint32_t* a, const uint32_t* b) {
    asm volatile("mma.sync.aligned.m16n8k16.row.col.f32.bf16.bf16.f32 "
        "{%0,%1,%2,%3}, {%4,%5,%6,%7}, {%8,%9}, {%0,%1,%2,%3};"
        : "+f"(c[0]), "+f"(c[1]), "+f"(c[2]), "+f"(c[3])
        : "r"(a[0]), "r"(a[1]), "r"(a[2]), "r"(a[3]), "r"(b[0]), "r"(b[1]));
}
__device__ __forceinline__ void ldsm4(uint32_t* r, uint32_t addr) {
    asm volatile("ldmatrix.sync.aligned.m8n8.x4.shared.b16 {%0,%1,%2,%3}, [%4];"
        : "=r"(r[0]), "=r"(r[1]), "=r"(r[2]), "=r"(r[3]) : "r"(addr));
}

// SMEM row stride 144B (72 bf16): conflict-free for LDSM 8-row x 16B phases.
#define RS 144

// ---------------- prep: split weights into [outer][k] bf16 hi/lo ------------
__global__ void prep_w1_kernel(const float* __restrict__ W1) {
    const int m2 = blockIdx.x, n = threadIdx.x;
    const float* Wm = W1 + (size_t)m2 * 16384;
    #pragma unroll
    for (int j = 0; j < 8; j++) {
        uint32_t p[8];
        #pragma unroll
        for (int kk = 0; kk < 8; kk++) p[kk] = fsplit_pack(Wm[(8 * j + kk) * 256 + n]);
        const int idx = (m2 * 256 + n) * 8 + j;
        g_w1hi[idx] = make_uint4(__byte_perm(p[0], p[1], 0x5410), __byte_perm(p[2], p[3], 0x5410),
                                 __byte_perm(p[4], p[5], 0x5410), __byte_perm(p[6], p[7], 0x5410));
        g_w1lo[idx] = make_uint4(__byte_perm(p[0], p[1], 0x7632), __byte_perm(p[2], p[3], 0x7632),
                                 __byte_perm(p[4], p[5], 0x7632), __byte_perm(p[6], p[7], 0x7632));
    }
}
__global__ void prep_w2_kernel(const float* __restrict__ W2) {
    const int n1 = blockIdx.x, tid = threadIdx.x;
    const int n2 = tid & 63, kq = tid >> 6;
    const float* Wn = W2 + (size_t)n1 * 16384;
    #pragma unroll
    for (int j = 0; j < 8; j++) {
        const int k0 = kq * 64 + j * 8;
        uint32_t p[8];
        #pragma unroll
        for (int kk = 0; kk < 8; kk++) p[kk] = fsplit_pack(Wn[(k0 + kk) * 64 + n2]);
        const int idx = (n1 * 64 + n2) * 32 + kq * 8 + j;
        g_w2hi[idx] = make_uint4(__byte_perm(p[0], p[1], 0x5410), __byte_perm(p[2], p[3], 0x5410),
                                 __byte_perm(p[4], p[5], 0x5410), __byte_perm(p[6], p[7], 0x5410));
        g_w2lo[idx] = make_uint4(__byte_perm(p[0], p[1], 0x7632), __byte_perm(p[2], p[3], 0x7632),
                                 __byte_perm(p[4], p[5], 0x7632), __byte_perm(p[6], p[7], 0x7632));
    }
}

// ---------------- MMA pass over 128xN tile, K=64, via ldmatrix --------------
// Aaddr/Baddr: smem u32 addrs including per-lane fragment offsets.
template <int NT>
__device__ __forceinline__ void mma_pass(uint32_t Aaddr, uint32_t Baddr,
                                         float acc[2][NT][4]) {
    #pragma unroll
    for (int ks = 0; ks < 4; ks++) {
        uint32_t a[2][4];
        ldsm4(a[0], Aaddr + ks * 32);
        ldsm4(a[1], Aaddr + 16 * RS + ks * 32);
        uint32_t b[NT][2];
        #pragma unroll
        for (int ntp = 0; ntp < NT / 2; ntp++) {
            uint32_t r[4];
            ldsm4(r, Baddr + ntp * 16 * RS + ks * 32);
            b[2 * ntp][0] = r[0]; b[2 * ntp][1] = r[1];
            b[2 * ntp + 1][0] = r[2]; b[2 * ntp + 1][1] = r[3];
        }
        #pragma unroll
        for (int mt = 0; mt < 2; mt++)
            #pragma unroll
            for (int nt = 0; nt < NT; nt++) mma16816(acc[mt][nt], a[mt], b[nt]);
    }
}

// ---------------- stage 1: tile 128(b) x 128(n), K=64 -----------------------
#define S1_AHI 0
#define S1_ALO 18432
#define S1_BHI 36864
#define S1_BLO 55296
#define S1_SMEM 73728

__global__ void __launch_bounds__(256, 2)
stage1_kernel(const float* __restrict__ x) {
    extern __shared__ char smem[];
    const uint32_t sb = (uint32_t)__cvta_generic_to_shared(smem);
    const int tid = threadIdx.x, wid = tid >> 5, lane = tid & 31;
    const int m2 = blockIdx.x, b0 = blockIdx.y * 128, nbase = blockIdx.z * 128;

    // B fill: pre-split images (L2-resident)
    {
        const uint4* bh = g_w1hi + (m2 * 256 + nbase) * 8;
        const uint4* bl = g_w1lo + (m2 * 256 + nbase) * 8;
        #pragma unroll
        for (int i = 0; i < 4; i++) {
            const int idx = tid + 256 * i;        // 1024 uint4
            const int row = idx >> 3, q = idx & 7;
            *(uint4*)(smem + S1_BHI + row * RS + q * 16) = bh[idx];
            *(uint4*)(smem + S1_BLO + row * RS + q * 16) = bl[idx];
        }
    }
    // A fill: x tile 128x64 fp32 -> hi/lo bf16
    #pragma unroll
    for (int i = 0; i < 8; i++) {
        const int idx = tid + 256 * i;            // 2048 float4
        const int row = idx >> 4, c4 = (idx & 15) << 2;
        float4 v = *(const float4*)(x + (size_t)(b0 + row) * 4096 + m2 * 64 + c4);
        uint32_t p0 = fsplit_pack(v.x), p1 = fsplit_pack(v.y),
                 p2 = fsplit_pack(v.z), p3 = fsplit_pack(v.w);
        *(uint2*)(smem + S1_AHI + row * RS + c4 * 2) =
            make_uint2(__byte_perm(p0, p1, 0x5410), __byte_perm(p2, p3, 0x5410));
        *(uint2*)(smem + S1_ALO + row * RS + c4 * 2) =
            make_uint2(__byte_perm(p0, p1, 0x7632), __byte_perm(p2, p3, 0x7632));
    }
    __syncthreads();

    const int wr = wid >> 1, wc = wid & 1, qr = lane >> 2, qc = lane & 3;
    const uint32_t laneA = (uint32_t)((wr * 32 + (lane & 15)) * RS + ((lane & 16) ? 16 : 0));
    const uint32_t laneB = (uint32_t)((wc * 64 + (lane & 7) + ((lane & 16) ? 8 : 0)) * RS +
                                      ((lane & 8) ? 16 : 0));
    float acc[2][8][4];
    #pragma unroll
    for (int mt = 0; mt < 2; mt++)
        #pragma unroll
        for (int nt = 0; nt < 8; nt++)
            #pragma unroll
            for (int r = 0; r < 4; r++) acc[mt][nt][r] = 0.f;

    mma_pass<8>(sb + S1_AHI + laneA, sb + S1_BHI + laneB, acc);
    mma_pass<8>(sb + S1_AHI + laneA, sb + S1_BLO + laneB, acc);
    mma_pass<8>(sb + S1_ALO + laneA, sb + S1_BHI + laneB, acc);

    // epilogue -> g_t[n1][m2][b][r]; half-warp runs are 128B contiguous.
    uint2* gt2 = (uint2*)g_t;
    #pragma unroll
    for (int mt = 0; mt < 2; mt++) {
        const size_t row0 = (size_t)(b0 + wr * 32 + mt * 16 + qr);
        #pragma unroll
        for (int nt = 0; nt < 8; nt++) {
            const int cg = nbase + wc * 64 + nt * 8 + qc * 2;   // n = n1*4 + r
            const size_t base = (((size_t)(cg >> 2) * 64 + m2) * 4096) * 4 + (cg & 3);
            gt2[(base + row0 * 4) >> 1] =
                make_uint2(fsplit_pack(acc[mt][nt][0]), fsplit_pack(acc[mt][nt][1]));
            gt2[(base + (row0 + 8) * 4) >> 1] =
                make_uint2(fsplit_pack(acc[mt][nt][2]), fsplit_pack(acc[mt][nt][3]));
        }
    }
}

// ---------------- stage 2: tile 128(b) x 64(n2), K=256 (4 x 64) -------------
#define S2_AHI 0
#define S2_ALO 18432
#define S2_BHI 36864                 // [chunk][64][RS] per half (9216 B/chunk)
#define S2_BLO 73728
#define S2_SMEM 110592

__global__ void __launch_bounds__(256, 2)
stage2_kernel(float* __restrict__ y) {
    extern __shared__ char smem[];
    const uint32_t sb = (uint32_t)__cvta_generic_to_shared(smem);
    const int tid = threadIdx.x, wid = tid >> 5, lane = tid & 31;
    const int n1 = blockIdx.x, b0 = blockIdx.y * 128;

    // B fill (once): chunked [chunk][n2][RS]
    {
        const uint4* bh = g_w2hi + n1 * 2048;
        const uint4* bl = g_w2lo + n1 * 2048;
        #pragma unroll
        for (int i = 0; i < 8; i++) {
            const int idx = tid + 256 * i;        // 2048 uint4
            const int n2 = idx >> 5, w = idx & 31;
            const int chunk = w >> 3, q = w & 7;
            const int dst = chunk * 9216 + n2 * RS + q * 16;
            *(uint4*)(smem + S2_BHI + dst) = bh[idx];
            *(uint4*)(smem + S2_BLO + dst) = bl[idx];
        }
    }

    const int wr = wid >> 1, wc = wid & 1, qr = lane >> 2, qc = lane & 3;
    const uint32_t laneA = (uint32_t)((wr * 32 + (lane & 15)) * RS + ((lane & 16) ? 16 : 0));
    const uint32_t laneB = (uint32_t)((wc * 32 + (lane & 7) + ((lane & 16) ? 8 : 0)) * RS +
                                      ((lane & 8) ? 16 : 0));
    float acc[2][4][4];
    #pragma unroll
    for (int mt = 0; mt < 2; mt++)
        #pragma unroll
        for (int nt = 0; nt < 4; nt++)
            #pragma unroll
            for (int r = 0; r < 4; r++) acc[mt][nt][r] = 0.f;

    for (int ch = 0; ch < 4; ch++) {
        if (ch > 0) __syncthreads();
        // A fill: chunk = m2 in [16ch, 16ch+16); fully coalesced 2KB runs.
        const uint4* tsrc = g_t + ((size_t)n1 * 64 + 16 * ch) * 4096 + b0;
        #pragma unroll
        for (int i = 0; i < 8; i++) {
            const int idx = tid + 256 * i;        // 2048 uint4
            const int m2l = idx >> 7, row = idx & 127;
            uint4 t4 = tsrc[(size_t)m2l * 4096 + row];
            *(uint2*)(smem + S2_AHI + row * RS + m2l * 8) =
                make_uint2(__byte_perm(t4.x, t4.y, 0x5410), __byte_perm(t4.z, t4.w, 0x5410));
            *(uint2*)(smem + S2_ALO + row * RS + m2l * 8) =
                make_uint2(__byte_perm(t4.x, t4.y, 0x7632), __byte_perm(t4.z, t4.w, 0x7632));
        }
        __syncthreads();

        const uint32_t BH = sb + S2_BHI + ch * 9216 + laneB;
        const uint32_t BL = sb + S2_BLO + ch * 9216 + laneB;
        mma_pass<4>(sb + S2_AHI + laneA, BH, acc);
        mma_pass<4>(sb + S2_AHI + laneA, BL, acc);
        mma_pass<4>(sb + S2_ALO + laneA, BH, acc);
    }

    // epilogue: y[b][n1*64 + n2]
    #pragma unroll
    for (int mt = 0; mt < 2; mt++) {
        const size_t row0 = (size_t)(b0 + wr * 32 + mt * 16 + qr);
        #pragma unroll
        for (int nt = 0; nt < 4; nt++) {
            const int col = n1 * 64 + wc * 32 + nt * 8 + qc * 2;
            *(float2*)(y + row0 * 4096 + col) = make_float2(acc[mt][nt][0], acc[mt][nt][1]);
            *(float2*)(y + (row0 + 8) * 4096 + col) = make_float2(acc[mt][nt][2], acc[mt][nt][3]);
        }
    }
}

// ---------------------------------------------------------------------------
extern "C" void kernel_launch(void* const* d_in, const int* in_sizes, int n_in,
                              void* d_out, int out_size) {
    const float* x  = (const float*)d_in[0];
    const float* W1 = (const float*)d_in[1];
    const float* W2 = (const float*)d_in[2];
    float* y = (float*)d_out;

    cudaFuncSetAttribute(stage1_kernel, cudaFuncAttributeMaxDynamicSharedMemorySize, S1_SMEM);
    cudaFuncSetAttribute(stage2_kernel, cudaFuncAttributeMaxDynamicSharedMemorySize, S2_SMEM);

    prep_w1_kernel<<<64, 256>>>(W1);
    prep_w2_kernel<<<64, 256>>>(W2);
    stage1_kernel<<<dim3(64, 32, 2), 256, S1_SMEM>>>(x);
    stage2_kernel<<<dim3(64, 32), 256, S2_SMEM>>>(y);
}

// round 7
// speedup vs baseline: 1.8048x; 1.1876x over previous
#include <cuda_runtime.h>
#include <cuda_bf16.h>
#include <cstdint>

// BTT layer: B=4096, M1=M2=N1=N2=64, R=4.
//   stage1 (per m2): C[4096x256] = x[:, m2*64:+64] @ W1[m2]   (K=64)
//   stage2 (per n1): y[:, n1*64:+64] = t[n1] @ W2[n1]         (K=256)
// bf16 hi/lo split, 3 passes -> ~6e-6 rel err. mma.sync.m16n8k16 + ldmatrix.
// t packed (hi|lo) u32, layout [n1][m2][b][r].
// R7: 4 slabs of 1024 b-rows, s1/s2 interleaved so t stays L2-resident
//     (64MB slab < 126MB L2); stage2 register-prefetches next A chunk.

#define NB 4096
#define SLAB 1024

__device__ uint4 g_t[16777216];     // 256MB: uint4 idx = (n1*64+m2)*4096 + b
__device__ uint4 g_w1hi[131072];    // [m2][n=256][k-octet=8] (2MB)
__device__ uint4 g_w1lo[131072];
__device__ uint4 g_w2hi[131072];    // [n1][n2=64][k-octet=32] (2MB)
__device__ uint4 g_w2lo[131072];

__device__ __forceinline__ uint32_t fsplit_pack(float v) {
    __nv_bfloat16 h = __float2bfloat16(v);
    float rem = v - __bfloat162float(h);
    __nv_bfloat16 l = __float2bfloat16(rem);
    return (uint32_t)__bfloat16_as_ushort(h) | ((uint32_t)__bfloat16_as_ushort(l) << 16);
}
__device__ __forceinline__ void mma16816(float* c, const uint32_t* a, const uint32_t* b) {
    asm volatile("mma.sync.aligned.m16n8k16.row.col.f32.bf16.bf16.f32 "
        "{%0,%1,%2,%3}, {%4,%5,%6,%7}, {%8,%9}, {%0,%1,%2,%3};"
        : "+f"(c[0]), "+f"(c[1]), "+f"(c[2]), "+f"(c[3])
        : "r"(a[0]), "r"(a[1]), "r"(a[2]), "r"(a[3]), "r"(b[0]), "r"(b[1]));
}
__device__ __forceinline__ void ldsm4(uint32_t* r, uint32_t addr) {
    asm volatile("ldmatrix.sync.aligned.m8n8.x4.shared.b16 {%0,%1,%2,%3}, [%4];"
        : "=r"(r[0]), "=r"(r[1]), "=r"(r[2]), "=r"(r[3]) : "r"(addr));
}

// SMEM row stride 144B (72 bf16): conflict-free for LDSM 8-row x 16B phases.
#define RS 144

// ---------------- prep: split weights into [outer][k] bf16 hi/lo ------------
__global__ void prep_w1_kernel(const float* __restrict__ W1) {
    const int m2 = blockIdx.x, n = threadIdx.x;
    const float* Wm = W1 + (size_t)m2 * 16384;
    #pragma unroll
    for (int j = 0; j < 8; j++) {
        uint32_t p[8];
        #pragma unroll
        for (int kk = 0; kk < 8; kk++) p[kk] = fsplit_pack(Wm[(8 * j + kk) * 256 + n]);
        const int idx = (m2 * 256 + n) * 8 + j;
        g_w1hi[idx] = make_uint4(__byte_perm(p[0], p[1], 0x5410), __byte_perm(p[2], p[3], 0x5410),
                                 __byte_perm(p[4], p[5], 0x5410), __byte_perm(p[6], p[7], 0x5410));
        g_w1lo[idx] = make_uint4(__byte_perm(p[0], p[1], 0x7632), __byte_perm(p[2], p[3], 0x7632),
                                 __byte_perm(p[4], p[5], 0x7632), __byte_perm(p[6], p[7], 0x7632));
    }
}
__global__ void prep_w2_kernel(const float* __restrict__ W2) {
    const int n1 = blockIdx.x, tid = threadIdx.x;
    const int n2 = tid & 63, kq = tid >> 6;
    const float* Wn = W2 + (size_t)n1 * 16384;
    #pragma unroll
    for (int j = 0; j < 8; j++) {
        const int k0 = kq * 64 + j * 8;
        uint32_t p[8];
        #pragma unroll
        for (int kk = 0; kk < 8; kk++) p[kk] = fsplit_pack(Wn[(k0 + kk) * 64 + n2]);
        const int idx = (n1 * 64 + n2) * 32 + kq * 8 + j;
        g_w2hi[idx] = make_uint4(__byte_perm(p[0], p[1], 0x5410), __byte_perm(p[2], p[3], 0x5410),
                                 __byte_perm(p[4], p[5], 0x5410), __byte_perm(p[6], p[7], 0x5410));
        g_w2lo[idx] = make_uint4(__byte_perm(p[0], p[1], 0x7632), __byte_perm(p[2], p[3], 0x7632),
                                 __byte_perm(p[4], p[5], 0x7632), __byte_perm(p[6], p[7], 0x7632));
    }
}

// ---------------- MMA pass over 128xN tile, K=64, via ldmatrix --------------
template <int NT>
__device__ __forceinline__ void mma_pass(uint32_t Aaddr, uint32_t Baddr,
                                         float acc[2][NT][4]) {
    #pragma unroll
    for (int ks = 0; ks < 4; ks++) {
        uint32_t a[2][4];
        ldsm4(a[0], Aaddr + ks * 32);
        ldsm4(a[1], Aaddr + 16 * RS + ks * 32);
        uint32_t b[NT][2];
        #pragma unroll
        for (int ntp = 0; ntp < NT / 2; ntp++) {
            uint32_t r[4];
            ldsm4(r, Baddr + ntp * 16 * RS + ks * 32);
            b[2 * ntp][0] = r[0]; b[2 * ntp][1] = r[1];
            b[2 * ntp + 1][0] = r[2]; b[2 * ntp + 1][1] = r[3];
        }
        #pragma unroll
        for (int mt = 0; mt < 2; mt++)
            #pragma unroll
            for (int nt = 0; nt < NT; nt++) mma16816(acc[mt][nt], a[mt], b[nt]);
    }
}

// ---------------- stage 1: tile 128(b) x 128(n), K=64 -----------------------
#define S1_AHI 0
#define S1_ALO 18432
#define S1_BHI 36864
#define S1_BLO 55296
#define S1_SMEM 73728

__global__ void __launch_bounds__(256, 2)
stage1_kernel(const float* __restrict__ x, int bslab) {
    extern __shared__ char smem[];
    const uint32_t sb = (uint32_t)__cvta_generic_to_shared(smem);
    const int tid = threadIdx.x, wid = tid >> 5, lane = tid & 31;
    const int m2 = blockIdx.x, b0 = bslab + blockIdx.y * 128, nbase = blockIdx.z * 128;

    {
        const uint4* bh = g_w1hi + (m2 * 256 + nbase) * 8;
        const uint4* bl = g_w1lo + (m2 * 256 + nbase) * 8;
        #pragma unroll
        for (int i = 0; i < 4; i++) {
            const int idx = tid + 256 * i;
            const int row = idx >> 3, q = idx & 7;
            *(uint4*)(smem + S1_BHI + row * RS + q * 16) = bh[idx];
            *(uint4*)(smem + S1_BLO + row * RS + q * 16) = bl[idx];
        }
    }
    #pragma unroll
    for (int i = 0; i < 8; i++) {
        const int idx = tid + 256 * i;
        const int row = idx >> 4, c4 = (idx & 15) << 2;
        float4 v = *(const float4*)(x + (size_t)(b0 + row) * 4096 + m2 * 64 + c4);
        uint32_t p0 = fsplit_pack(v.x), p1 = fsplit_pack(v.y),
                 p2 = fsplit_pack(v.z), p3 = fsplit_pack(v.w);
        *(uint2*)(smem + S1_AHI + row * RS + c4 * 2) =
            make_uint2(__byte_perm(p0, p1, 0x5410), __byte_perm(p2, p3, 0x5410));
        *(uint2*)(smem + S1_ALO + row * RS + c4 * 2) =
            make_uint2(__byte_perm(p0, p1, 0x7632), __byte_perm(p2, p3, 0x7632));
    }
    __syncthreads();

    const int wr = wid >> 1, wc = wid & 1, qr = lane >> 2, qc = lane & 3;
    const uint32_t laneA = (uint32_t)((wr * 32 + (lane & 15)) * RS + ((lane & 16) ? 16 : 0));
    const uint32_t laneB = (uint32_t)((wc * 64 + (lane & 7) + ((lane & 16) ? 8 : 0)) * RS +
                                      ((lane & 8) ? 16 : 0));
    float acc[2][8][4];
    #pragma unroll
    for (int mt = 0; mt < 2; mt++)
        #pragma unroll
        for (int nt = 0; nt < 8; nt++)
            #pragma unroll
            for (int r = 0; r < 4; r++) acc[mt][nt][r] = 0.f;

    mma_pass<8>(sb + S1_AHI + laneA, sb + S1_BHI + laneB, acc);
    mma_pass<8>(sb + S1_AHI + laneA, sb + S1_BLO + laneB, acc);
    mma_pass<8>(sb + S1_ALO + laneA, sb + S1_BHI + laneB, acc);

    uint2* gt2 = (uint2*)g_t;
    #pragma unroll
    for (int mt = 0; mt < 2; mt++) {
        const size_t row0 = (size_t)(b0 + wr * 32 + mt * 16 + qr);
        #pragma unroll
        for (int nt = 0; nt < 8; nt++) {
            const int cg = nbase + wc * 64 + nt * 8 + qc * 2;   // n = n1*4 + r
            const size_t base = (((size_t)(cg >> 2) * 64 + m2) * 4096) * 4 + (cg & 3);
            gt2[(base + row0 * 4) >> 1] =
                make_uint2(fsplit_pack(acc[mt][nt][0]), fsplit_pack(acc[mt][nt][1]));
            gt2[(base + (row0 + 8) * 4) >> 1] =
                make_uint2(fsplit_pack(acc[mt][nt][2]), fsplit_pack(acc[mt][nt][3]));
        }
    }
}

// ---------------- stage 2: tile 128(b) x 64(n2), K=256 (4 x 64) -------------
#define S2_AHI 0
#define S2_ALO 18432
#define S2_BHI 36864                 // [chunk][64][RS] per half (9216 B/chunk)
#define S2_BLO 73728
#define S2_SMEM 110592

__global__ void __launch_bounds__(256, 2)
stage2_kernel(float* __restrict__ y, int bslab) {
    extern __shared__ char smem[];
    const uint32_t sb = (uint32_t)__cvta_generic_to_shared(smem);
    const int tid = threadIdx.x, wid = tid >> 5, lane = tid & 31;
    const int n1 = blockIdx.x, b0 = bslab + blockIdx.y * 128;

    // B fill (once): chunked [chunk][n2][RS]
    {
        const uint4* bh = g_w2hi + n1 * 2048;
        const uint4* bl = g_w2lo + n1 * 2048;
        #pragma unroll
        for (int i = 0; i < 8; i++) {
            const int idx = tid + 256 * i;
            const int n2 = idx >> 5, w = idx & 31;
            const int chunk = w >> 3, q = w & 7;
            const int dst = chunk * 9216 + n2 * RS + q * 16;
            *(uint4*)(smem + S2_BHI + dst) = bh[idx];
            *(uint4*)(smem + S2_BLO + dst) = bl[idx];
        }
    }

    const int wr = wid >> 1, wc = wid & 1, qr = lane >> 2, qc = lane & 3;
    const uint32_t laneA = (uint32_t)((wr * 32 + (lane & 15)) * RS + ((lane & 16) ? 16 : 0));
    const uint32_t laneB = (uint32_t)((wc * 32 + (lane & 7) + ((lane & 16) ? 8 : 0)) * RS +
                                      ((lane & 8) ? 16 : 0));
    float acc[2][4][4];
    #pragma unroll
    for (int mt = 0; mt < 2; mt++)
        #pragma unroll
        for (int nt = 0; nt < 4; nt++)
            #pragma unroll
            for (int r = 0; r < 4; r++) acc[mt][nt][r] = 0.f;

    // A prefetch pipeline: regs hold next chunk's 8 uint4 per thread.
    const uint4* tb0 = g_t + (size_t)n1 * 64 * 4096 + b0;
    uint4 pref[8];
    #pragma unroll
    for (int i = 0; i < 8; i++) {
        const int idx = tid + 256 * i;
        pref[i] = tb0[(size_t)(idx >> 7) * 4096 + (idx & 127)];
    }

    for (int ch = 0; ch < 4; ch++) {
        // STS current chunk from regs (deinterleave hi/lo)
        #pragma unroll
        for (int i = 0; i < 8; i++) {
            const int idx = tid + 256 * i;
            const int row = idx & 127, m2l = idx >> 7;
            uint4 t4 = pref[i];
            *(uint2*)(smem + S2_AHI + row * RS + m2l * 8) =
                make_uint2(__byte_perm(t4.x, t4.y, 0x5410), __byte_perm(t4.z, t4.w, 0x5410));
            *(uint2*)(smem + S2_ALO + row * RS + m2l * 8) =
                make_uint2(__byte_perm(t4.x, t4.y, 0x7632), __byte_perm(t4.z, t4.w, 0x7632));
        }
        __syncthreads();
        // Issue next chunk's loads; latency overlaps the MMA below.
        if (ch < 3) {
            const uint4* ts = tb0 + (size_t)(16 * (ch + 1)) * 4096;
            #pragma unroll
            for (int i = 0; i < 8; i++) {
                const int idx = tid + 256 * i;
                pref[i] = ts[(size_t)(idx >> 7) * 4096 + (idx & 127)];
            }
        }

        const uint32_t BH = sb + S2_BHI + ch * 9216 + laneB;
        const uint32_t BL = sb + S2_BLO + ch * 9216 + laneB;
        mma_pass<4>(sb + S2_AHI + laneA, BH, acc);
        mma_pass<4>(sb + S2_AHI + laneA, BL, acc);
        mma_pass<4>(sb + S2_ALO + laneA, BH, acc);
        __syncthreads();   // MMA reads done before next STS overwrite
    }

    // epilogue: y[b][n1*64 + n2]
    #pragma unroll
    for (int mt = 0; mt < 2; mt++) {
        const size_t row0 = (size_t)(b0 + wr * 32 + mt * 16 + qr);
        #pragma unroll
        for (int nt = 0; nt < 4; nt++) {
            const int col = n1 * 64 + wc * 32 + nt * 8 + qc * 2;
            *(float2*)(y + row0 * 4096 + col) = make_float2(acc[mt][nt][0], acc[mt][nt][1]);
            *(float2*)(y + (row0 + 8) * 4096 + col) = make_float2(acc[mt][nt][2], acc[mt][nt][3]);
        }
    }
}

// ---------------------------------------------------------------------------
extern "C" void kernel_launch(void* const* d_in, const int* in_sizes, int n_in,
                              void* d_out, int out_size) {
    const float* x  = (const float*)d_in[0];
    const float* W1 = (const float*)d_in[1];
    const float* W2 = (const float*)d_in[2];
    float* y = (float*)d_out;

    cudaFuncSetAttribute(stage1_kernel, cudaFuncAttributeMaxDynamicSharedMemorySize, S1_SMEM);
    cudaFuncSetAttribute(stage2_kernel, cudaFuncAttributeMaxDynamicSharedMemorySize, S2_SMEM);

    prep_w1_kernel<<<64, 256>>>(W1);
    prep_w2_kernel<<<64, 256>>>(W2);
    // Interleave slabs so each slab's t (64MB) is consumed while L2-resident.
    for (int s = 0; s < 4; s++) {
        stage1_kernel<<<dim3(64, SLAB / 128, 2), 256, S1_SMEM>>>(x, s * SLAB);
        stage2_kernel<<<dim3(64, SLAB / 128), 256, S2_SMEM>>>(y, s * SLAB);
    }
}

// round 8
// speedup vs baseline: 1.9894x; 1.1023x over previous
#include <cuda_runtime.h>
#include <cuda_bf16.h>
#include <cstdint>

// BTT layer: B=4096, M1=M2=N1=N2=64, R=4.
//   stage1 (per m2): C[4096x256] = x[:, m2*64:+64] @ W1[m2]   (K=64)
//   stage2 (per n1): y[:, n1*64:+64] = t[n1] @ W2[n1]         (K=256)
// bf16 hi/lo split, 3 combos merged over shared fragments -> ~6e-6 rel err.
// t packed (hi|lo) u32, layout [n1][m2][b][r]. 4 slabs interleaved (L2-resident t).

#define NB 4096
#define SLAB 1024

__device__ uint4 g_t[16777216];     // 256MB: uint4 idx = (n1*64+m2)*4096 + b
__device__ uint4 g_w1hi[131072];    // [m2][n=256][k-octet=8] (2MB)
__device__ uint4 g_w1lo[131072];
__device__ uint4 g_w2hi[131072];    // [n1][n2=64][k-octet=32] (2MB)
__device__ uint4 g_w2lo[131072];

__device__ __forceinline__ uint32_t fsplit_pack(float v) {
    __nv_bfloat16 h = __float2bfloat16(v);
    float rem = v - __bfloat162float(h);
    __nv_bfloat16 l = __float2bfloat16(rem);
    return (uint32_t)__bfloat16_as_ushort(h) | ((uint32_t)__bfloat16_as_ushort(l) << 16);
}
__device__ __forceinline__ void mma16816(float* c, const uint32_t* a, const uint32_t* b) {
    asm volatile("mma.sync.aligned.m16n8k16.row.col.f32.bf16.bf16.f32 "
        "{%0,%1,%2,%3}, {%4,%5,%6,%7}, {%8,%9}, {%0,%1,%2,%3};"
        : "+f"(c[0]), "+f"(c[1]), "+f"(c[2]), "+f"(c[3])
        : "r"(a[0]), "r"(a[1]), "r"(a[2]), "r"(a[3]), "r"(b[0]), "r"(b[1]));
}
__device__ __forceinline__ void ldsm4(uint32_t* r, uint32_t addr) {
    asm volatile("ldmatrix.sync.aligned.m8n8.x4.shared.b16 {%0,%1,%2,%3}, [%4];"
        : "=r"(r[0]), "=r"(r[1]), "=r"(r[2]), "=r"(r[3]) : "r"(addr));
}

// SMEM row stride 144B (72 bf16): conflict-free for LDSM 8-row x 16B phases.
#define RS 144

// ---------------- prep: split weights into [outer][k] bf16 hi/lo ------------
__global__ void prep_w1_kernel(const float* __restrict__ W1) {
    const int m2 = blockIdx.x, n = threadIdx.x;
    const float* Wm = W1 + (size_t)m2 * 16384;
    #pragma unroll
    for (int j = 0; j < 8; j++) {
        uint32_t p[8];
        #pragma unroll
        for (int kk = 0; kk < 8; kk++) p[kk] = fsplit_pack(Wm[(8 * j + kk) * 256 + n]);
        const int idx = (m2 * 256 + n) * 8 + j;
        g_w1hi[idx] = make_uint4(__byte_perm(p[0], p[1], 0x5410), __byte_perm(p[2], p[3], 0x5410),
                                 __byte_perm(p[4], p[5], 0x5410), __byte_perm(p[6], p[7], 0x5410));
        g_w1lo[idx] = make_uint4(__byte_perm(p[0], p[1], 0x7632), __byte_perm(p[2], p[3], 0x7632),
                                 __byte_perm(p[4], p[5], 0x7632), __byte_perm(p[6], p[7], 0x7632));
    }
}
__global__ void prep_w2_kernel(const float* __restrict__ W2) {
    const int n1 = blockIdx.x, tid = threadIdx.x;
    const int n2 = tid & 63, kq = tid >> 6;
    const float* Wn = W2 + (size_t)n1 * 16384;
    #pragma unroll
    for (int j = 0; j < 8; j++) {
        const int k0 = kq * 64 + j * 8;
        uint32_t p[8];
        #pragma unroll
        for (int kk = 0; kk < 8; kk++) p[kk] = fsplit_pack(Wn[(k0 + kk) * 64 + n2]);
        const int idx = (n1 * 64 + n2) * 32 + kq * 8 + j;
        g_w2hi[idx] = make_uint4(__byte_perm(p[0], p[1], 0x5410), __byte_perm(p[2], p[3], 0x5410),
                                 __byte_perm(p[4], p[5], 0x5410), __byte_perm(p[6], p[7], 0x5410));
        g_w2lo[idx] = make_uint4(__byte_perm(p[0], p[1], 0x7632), __byte_perm(p[2], p[3], 0x7632),
                                 __byte_perm(p[4], p[5], 0x7632), __byte_perm(p[6], p[7], 0x7632));
    }
}

// ---------------- merged 3-combo MMA passes (shared fragments) --------------
// NT=4 (stage2): full merge, 8 LDSM / 24 MMA per ks.
__device__ __forceinline__ void mma_merged4(uint32_t AH, uint32_t AL,
                                            uint32_t BH, uint32_t BL,
                                            float acc[2][4][4]) {
    #pragma unroll
    for (int ks = 0; ks < 4; ks++) {
        uint32_t ah[2][4], al[2][4];
        ldsm4(ah[0], AH + ks * 32);
        ldsm4(ah[1], AH + 16 * RS + ks * 32);
        ldsm4(al[0], AL + ks * 32);
        ldsm4(al[1], AL + 16 * RS + ks * 32);
        uint32_t bh[4][2], bl[4][2];
        #pragma unroll
        for (int p = 0; p < 2; p++) {
            uint32_t r[4];
            ldsm4(r, BH + p * 16 * RS + ks * 32);
            bh[2 * p][0] = r[0]; bh[2 * p][1] = r[1];
            bh[2 * p + 1][0] = r[2]; bh[2 * p + 1][1] = r[3];
            ldsm4(r, BL + p * 16 * RS + ks * 32);
            bl[2 * p][0] = r[0]; bl[2 * p][1] = r[1];
            bl[2 * p + 1][0] = r[2]; bl[2 * p + 1][1] = r[3];
        }
        #pragma unroll
        for (int mt = 0; mt < 2; mt++)
            #pragma unroll
            for (int nt = 0; nt < 4; nt++) {
                mma16816(acc[mt][nt], ah[mt], bh[nt]);
                mma16816(acc[mt][nt], al[mt], bh[nt]);
                mma16816(acc[mt][nt], ah[mt], bl[nt]);
            }
    }
}
// NT=8 (stage1): two register-bounded groups, 12 LDSM / 48 MMA per ks.
__device__ __forceinline__ void mma_merged8(uint32_t AH, uint32_t AL,
                                            uint32_t BH, uint32_t BL,
                                            float acc[2][8][4]) {
    #pragma unroll
    for (int ks = 0; ks < 4; ks++) {
        uint32_t ah[2][4], al[2][4];
        ldsm4(ah[0], AH + ks * 32);
        ldsm4(ah[1], AH + 16 * RS + ks * 32);
        ldsm4(al[0], AL + ks * 32);
        ldsm4(al[1], AL + 16 * RS + ks * 32);
        {   // group 1: (Ah + Al) x Bh
            uint32_t b[8][2];
            #pragma unroll
            for (int p = 0; p < 4; p++) {
                uint32_t r[4];
                ldsm4(r, BH + p * 16 * RS + ks * 32);
                b[2 * p][0] = r[0]; b[2 * p][1] = r[1];
                b[2 * p + 1][0] = r[2]; b[2 * p + 1][1] = r[3];
            }
            #pragma unroll
            for (int mt = 0; mt < 2; mt++)
                #pragma unroll
                for (int nt = 0; nt < 8; nt++) {
                    mma16816(acc[mt][nt], ah[mt], b[nt]);
                    mma16816(acc[mt][nt], al[mt], b[nt]);
                }
        }
        {   // group 2: Ah x Bl
            uint32_t b[8][2];
            #pragma unroll
            for (int p = 0; p < 4; p++) {
                uint32_t r[4];
                ldsm4(r, BL + p * 16 * RS + ks * 32);
                b[2 * p][0] = r[0]; b[2 * p][1] = r[1];
                b[2 * p + 1][0] = r[2]; b[2 * p + 1][1] = r[3];
            }
            #pragma unroll
            for (int mt = 0; mt < 2; mt++)
                #pragma unroll
                for (int nt = 0; nt < 8; nt++)
                    mma16816(acc[mt][nt], ah[mt], b[nt]);
        }
    }
}

// ---------------- stage 1: tile 128(b) x 128(n), K=64 -----------------------
#define S1_AHI 0
#define S1_ALO 18432
#define S1_BHI 36864
#define S1_BLO 55296
#define S1_SMEM 73728

__global__ void __launch_bounds__(256, 2)
stage1_kernel(const float* __restrict__ x, int bslab) {
    extern __shared__ char smem[];
    const uint32_t sb = (uint32_t)__cvta_generic_to_shared(smem);
    const int tid = threadIdx.x, wid = tid >> 5, lane = tid & 31;
    const int m2 = blockIdx.x, b0 = bslab + blockIdx.y * 128, nbase = blockIdx.z * 128;

    {
        const uint4* bh = g_w1hi + (m2 * 256 + nbase) * 8;
        const uint4* bl = g_w1lo + (m2 * 256 + nbase) * 8;
        #pragma unroll
        for (int i = 0; i < 4; i++) {
            const int idx = tid + 256 * i;
            const int row = idx >> 3, q = idx & 7;
            *(uint4*)(smem + S1_BHI + row * RS + q * 16) = bh[idx];
            *(uint4*)(smem + S1_BLO + row * RS + q * 16) = bl[idx];
        }
    }
    #pragma unroll
    for (int i = 0; i < 8; i++) {
        const int idx = tid + 256 * i;
        const int row = idx >> 4, c4 = (idx & 15) << 2;
        float4 v = *(const float4*)(x + (size_t)(b0 + row) * 4096 + m2 * 64 + c4);
        uint32_t p0 = fsplit_pack(v.x), p1 = fsplit_pack(v.y),
                 p2 = fsplit_pack(v.z), p3 = fsplit_pack(v.w);
        *(uint2*)(smem + S1_AHI + row * RS + c4 * 2) =
            make_uint2(__byte_perm(p0, p1, 0x5410), __byte_perm(p2, p3, 0x5410));
        *(uint2*)(smem + S1_ALO + row * RS + c4 * 2) =
            make_uint2(__byte_perm(p0, p1, 0x7632), __byte_perm(p2, p3, 0x7632));
    }
    __syncthreads();

    const int wr = wid >> 1, wc = wid & 1, qr = lane >> 2, qc = lane & 3;
    const uint32_t laneA = (uint32_t)((wr * 32 + (lane & 15)) * RS + ((lane & 16) ? 16 : 0));
    const uint32_t laneB = (uint32_t)((wc * 64 + (lane & 7) + ((lane & 16) ? 8 : 0)) * RS +
                                      ((lane & 8) ? 16 : 0));
    float acc[2][8][4];
    #pragma unroll
    for (int mt = 0; mt < 2; mt++)
        #pragma unroll
        for (int nt = 0; nt < 8; nt++)
            #pragma unroll
            for (int r = 0; r < 4; r++) acc[mt][nt][r] = 0.f;

    mma_merged8(sb + S1_AHI + laneA, sb + S1_ALO + laneA,
                sb + S1_BHI + laneB, sb + S1_BLO + laneB, acc);

    uint2* gt2 = (uint2*)g_t;
    #pragma unroll
    for (int mt = 0; mt < 2; mt++) {
        const size_t row0 = (size_t)(b0 + wr * 32 + mt * 16 + qr);
        #pragma unroll
        for (int nt = 0; nt < 8; nt++) {
            const int cg = nbase + wc * 64 + nt * 8 + qc * 2;   // n = n1*4 + r
            const size_t base = (((size_t)(cg >> 2) * 64 + m2) * 4096) * 4 + (cg & 3);
            gt2[(base + row0 * 4) >> 1] =
                make_uint2(fsplit_pack(acc[mt][nt][0]), fsplit_pack(acc[mt][nt][1]));
            gt2[(base + (row0 + 8) * 4) >> 1] =
                make_uint2(fsplit_pack(acc[mt][nt][2]), fsplit_pack(acc[mt][nt][3]));
        }
    }
}

// ---------------- stage 2: tile 128(b) x 64(n2), K=256 (4 x 64) -------------
#define S2_AHI 0
#define S2_ALO 18432
#define S2_BHI 36864                 // [chunk][64][RS] per half (9216 B/chunk)
#define S2_BLO 73728
#define S2_SMEM 110592

__global__ void __launch_bounds__(256, 2)
stage2_kernel(float* __restrict__ y, int bslab) {
    extern __shared__ char smem[];
    const uint32_t sb = (uint32_t)__cvta_generic_to_shared(smem);
    const int tid = threadIdx.x, wid = tid >> 5, lane = tid & 31;
    const int n1 = blockIdx.x, b0 = bslab + blockIdx.y * 128;

    // B fill (once): chunked [chunk][n2][RS]
    {
        const uint4* bh = g_w2hi + n1 * 2048;
        const uint4* bl = g_w2lo + n1 * 2048;
        #pragma unroll
        for (int i = 0; i < 8; i++) {
            const int idx = tid + 256 * i;
            const int n2 = idx >> 5, w = idx & 31;
            const int chunk = w >> 3, q = w & 7;
            const int dst = chunk * 9216 + n2 * RS + q * 16;
            *(uint4*)(smem + S2_BHI + dst) = bh[idx];
            *(uint4*)(smem + S2_BLO + dst) = bl[idx];
        }
    }

    const int wr = wid >> 1, wc = wid & 1, qr = lane >> 2, qc = lane & 3;
    const uint32_t laneA = (uint32_t)((wr * 32 + (lane & 15)) * RS + ((lane & 16) ? 16 : 0));
    const uint32_t laneB = (uint32_t)((wc * 32 + (lane & 7) + ((lane & 16) ? 8 : 0)) * RS +
                                      ((lane & 8) ? 16 : 0));
    float acc[2][4][4];
    #pragma unroll
    for (int mt = 0; mt < 2; mt++)
        #pragma unroll
        for (int nt = 0; nt < 4; nt++)
            #pragma unroll
            for (int r = 0; r < 4; r++) acc[mt][nt][r] = 0.f;

    // A prefetch pipeline: regs hold next chunk's 8 uint4 per thread.
    const uint4* tb0 = g_t + (size_t)n1 * 64 * 4096 + b0;
    uint4 pref[8];
    #pragma unroll
    for (int i = 0; i < 8; i++) {
        const int idx = tid + 256 * i;
        pref[i] = tb0[(size_t)(idx >> 7) * 4096 + (idx & 127)];
    }

    for (int ch = 0; ch < 4; ch++) {
        // STS current chunk from regs (deinterleave hi/lo)
        #pragma unroll
        for (int i = 0; i < 8; i++) {
            const int idx = tid + 256 * i;
            const int row = idx & 127, m2l = idx >> 7;
            uint4 t4 = pref[i];
            *(uint2*)(smem + S2_AHI + row * RS + m2l * 8) =
                make_uint2(__byte_perm(t4.x, t4.y, 0x5410), __byte_perm(t4.z, t4.w, 0x5410));
            *(uint2*)(smem + S2_ALO + row * RS + m2l * 8) =
                make_uint2(__byte_perm(t4.x, t4.y, 0x7632), __byte_perm(t4.z, t4.w, 0x7632));
        }
        __syncthreads();
        // Issue next chunk's loads; latency overlaps the MMA below.
        if (ch < 3) {
            const uint4* ts = tb0 + (size_t)(16 * (ch + 1)) * 4096;
            #pragma unroll
            for (int i = 0; i < 8; i++) {
                const int idx = tid + 256 * i;
                pref[i] = ts[(size_t)(idx >> 7) * 4096 + (idx & 127)];
            }
        }

        mma_merged4(sb + S2_AHI + laneA, sb + S2_ALO + laneA,
                    sb + S2_BHI + ch * 9216 + laneB, sb + S2_BLO + ch * 9216 + laneB, acc);
        __syncthreads();   // MMA reads done before next STS overwrite
    }

    // epilogue: y[b][n1*64 + n2]
    #pragma unroll
    for (int mt = 0; mt < 2; mt++) {
        const size_t row0 = (size_t)(b0 + wr * 32 + mt * 16 + qr);
        #pragma unroll
        for (int nt = 0; nt < 4; nt++) {
            const int col = n1 * 64 + wc * 32 + nt * 8 + qc * 2;
            *(float2*)(y + row0 * 4096 + col) = make_float2(acc[mt][nt][0], acc[mt][nt][1]);
            *(float2*)(y + (row0 + 8) * 4096 + col) = make_float2(acc[mt][nt][2], acc[mt][nt][3]);
        }
    }
}

// ---------------------------------------------------------------------------
extern "C" void kernel_launch(void* const* d_in, const int* in_sizes, int n_in,
                              void* d_out, int out_size) {
    const float* x  = (const float*)d_in[0];
    const float* W1 = (const float*)d_in[1];
    const float* W2 = (const float*)d_in[2];
    float* y = (float*)d_out;

    cudaFuncSetAttribute(stage1_kernel, cudaFuncAttributeMaxDynamicSharedMemorySize, S1_SMEM);
    cudaFuncSetAttribute(stage2_kernel, cudaFuncAttributeMaxDynamicSharedMemorySize, S2_SMEM);

    prep_w1_kernel<<<64, 256>>>(W1);
    prep_w2_kernel<<<64, 256>>>(W2);
    // Interleave slabs so each slab's t (64MB) is consumed while L2-resident.
    for (int s = 0; s < 4; s++) {
        stage1_kernel<<<dim3(64, SLAB / 128, 2), 256, S1_SMEM>>>(x, s * SLAB);
        stage2_kernel<<<dim3(64, SLAB / 128), 256, S2_SMEM>>>(y, s * SLAB);
    }
}

// round 10
// speedup vs baseline: 2.2753x; 1.1437x over previous
#include <cuda_runtime.h>
#include <cuda_bf16.h>
#include <cstdint>

// BTT layer: B=4096, M1=M2=N1=N2=64, R=4.
//   stage1 (per m2): C[4096x256] = x[:, m2*64:+64] @ W1[m2]   (K=64)
//   stage2 (per n1): y[:, n1*64:+64] = t[n1] @ W2[n1]         (K=256)
// bf16 hi/lo split, 3 combos merged -> ~6e-6 rel err.
// t packed (hi|lo) u32, layout [n1][m2][b][r]; 4 slabs interleaved (L2-resident).
// R9: A fragments built DIRECTLY from global (coalesced L2 hits) -> no A smem,
//     no mainloop barriers in either stage.

#define NB 4096
#define SLAB 1024

__device__ uint4 g_t[16777216];     // 256MB: uint4 idx = (n1*64+m2)*4096 + b
__device__ uint4 g_w1hi[131072];    // [m2][n=256][k-octet=8] (2MB)
__device__ uint4 g_w1lo[131072];
__device__ uint4 g_w2hi[131072];    // [n1][n2=64][k-octet=32] (2MB)
__device__ uint4 g_w2lo[131072];

__device__ __forceinline__ uint32_t fsplit_pack(float v) {
    __nv_bfloat16 h = __float2bfloat16(v);
    float rem = v - __bfloat162float(h);
    __nv_bfloat16 l = __float2bfloat16(rem);
    return (uint32_t)__bfloat16_as_ushort(h) | ((uint32_t)__bfloat16_as_ushort(l) << 16);
}
__device__ __forceinline__ void mma16816(float* c, const uint32_t* a, const uint32_t* b) {
    asm volatile("mma.sync.aligned.m16n8k16.row.col.f32.bf16.bf16.f32 "
        "{%0,%1,%2,%3}, {%4,%5,%6,%7}, {%8,%9}, {%0,%1,%2,%3};"
        : "+f"(c[0]), "+f"(c[1]), "+f"(c[2]), "+f"(c[3])
        : "r"(a[0]), "r"(a[1]), "r"(a[2]), "r"(a[3]), "r"(b[0]), "r"(b[1]));
}
__device__ __forceinline__ void ldsm4(uint32_t* r, uint32_t addr) {
    asm volatile("ldmatrix.sync.aligned.m8n8.x4.shared.b16 {%0,%1,%2,%3}, [%4];"
        : "=r"(r[0]), "=r"(r[1]), "=r"(r[2]), "=r"(r[3]) : "r"(addr));
}

// SMEM row stride 144B (72 bf16): conflict-free for LDSM 8-row x 16B phases.
#define RS 144

// ---------------- prep: split weights into [outer][k] bf16 hi/lo ------------
__global__ void prep_w1_kernel(const float* __restrict__ W1) {
    const int m2 = blockIdx.x, n = threadIdx.x;
    const float* Wm = W1 + (size_t)m2 * 16384;
    #pragma unroll
    for (int j = 0; j < 8; j++) {
        uint32_t p[8];
        #pragma unroll
        for (int kk = 0; kk < 8; kk++) p[kk] = fsplit_pack(Wm[(8 * j + kk) * 256 + n]);
        const int idx = (m2 * 256 + n) * 8 + j;
        g_w1hi[idx] = make_uint4(__byte_perm(p[0], p[1], 0x5410), __byte_perm(p[2], p[3], 0x5410),
                                 __byte_perm(p[4], p[5], 0x5410), __byte_perm(p[6], p[7], 0x5410));
        g_w1lo[idx] = make_uint4(__byte_perm(p[0], p[1], 0x7632), __byte_perm(p[2], p[3], 0x7632),
                                 __byte_perm(p[4], p[5], 0x7632), __byte_perm(p[6], p[7], 0x7632));
    }
}
__global__ void prep_w2_kernel(const float* __restrict__ W2) {
    const int n1 = blockIdx.x, tid = threadIdx.x;
    const int n2 = tid & 63, kq = tid >> 6;
    const float* Wn = W2 + (size_t)n1 * 16384;
    #pragma unroll
    for (int j = 0; j < 8; j++) {
        const int k0 = kq * 64 + j * 8;
        uint32_t p[8];
        #pragma unroll
        for (int kk = 0; kk < 8; kk++) p[kk] = fsplit_pack(Wn[(k0 + kk) * 64 + n2]);
        const int idx = (n1 * 64 + n2) * 32 + kq * 8 + j;
        g_w2hi[idx] = make_uint4(__byte_perm(p[0], p[1], 0x5410), __byte_perm(p[2], p[3], 0x5410),
                                 __byte_perm(p[4], p[5], 0x5410), __byte_perm(p[6], p[7], 0x5410));
        g_w2lo[idx] = make_uint4(__byte_perm(p[0], p[1], 0x7632), __byte_perm(p[2], p[3], 0x7632),
                                 __byte_perm(p[4], p[5], 0x7632), __byte_perm(p[6], p[7], 0x7632));
    }
}

// ---------------- stage 1: tile 128(b) x 128(n), K=64 -----------------------
// SMEM: B tiles only (hi+lo), A fragments direct from x.
#define S1_BHI 0
#define S1_BLO 18432
#define S1_SMEM 36864

__global__ void __launch_bounds__(256, 2)
stage1_kernel(const float* __restrict__ x, int bslab) {
    extern __shared__ char smem[];
    const uint32_t sb = (uint32_t)__cvta_generic_to_shared(smem);
    const int tid = threadIdx.x, wid = tid >> 5, lane = tid & 31;
    const int m2 = blockIdx.x, b0 = bslab + blockIdx.y * 128, nbase = blockIdx.z * 128;

    {   // B fill: pre-split images (L2-resident)
        const uint4* bh = g_w1hi + (m2 * 256 + nbase) * 8;
        const uint4* bl = g_w1lo + (m2 * 256 + nbase) * 8;
        #pragma unroll
        for (int i = 0; i < 4; i++) {
            const int idx = tid + 256 * i;
            const int row = idx >> 3, q = idx & 7;
            *(uint4*)(smem + S1_BHI + row * RS + q * 16) = bh[idx];
            *(uint4*)(smem + S1_BLO + row * RS + q * 16) = bl[idx];
        }
    }
    __syncthreads();   // the only barrier

    const int wr = wid >> 1, wc = wid & 1, qr = lane >> 2, qc = lane & 3;
    const uint32_t laneB = (uint32_t)((wc * 64 + (lane & 7) + ((lane & 16) ? 8 : 0)) * RS +
                                      ((lane & 8) ? 16 : 0));
    const int row0 = b0 + wr * 32 + qr;

    float acc[2][8][4];
    #pragma unroll
    for (int mt = 0; mt < 2; mt++)
        #pragma unroll
        for (int nt = 0; nt < 8; nt++)
            #pragma unroll
            for (int r = 0; r < 4; r++) acc[mt][nt][r] = 0.f;

    #pragma unroll
    for (int ks = 0; ks < 4; ks++) {
        const int k0 = ks * 16 + 2 * qc;
        // A fragments straight from x (fp32 -> hi/lo split in regs)
        uint32_t ah[2][4], al[2][4];
        #pragma unroll
        for (int mt = 0; mt < 2; mt++) {
            const float* xr = x + (size_t)(row0 + mt * 16) * 4096 + m2 * 64;
            float2 f0 = *(const float2*)(xr + k0);
            float2 f1 = *(const float2*)(xr + (size_t)8 * 4096 + k0);
            float2 f2 = *(const float2*)(xr + k0 + 8);
            float2 f3 = *(const float2*)(xr + (size_t)8 * 4096 + k0 + 8);
            uint32_t q0 = fsplit_pack(f0.x), q1 = fsplit_pack(f0.y);
            uint32_t q2 = fsplit_pack(f1.x), q3 = fsplit_pack(f1.y);
            uint32_t q4 = fsplit_pack(f2.x), q5 = fsplit_pack(f2.y);
            uint32_t q6 = fsplit_pack(f3.x), q7 = fsplit_pack(f3.y);
            ah[mt][0] = __byte_perm(q0, q1, 0x5410); al[mt][0] = __byte_perm(q0, q1, 0x7632);
            ah[mt][1] = __byte_perm(q2, q3, 0x5410); al[mt][1] = __byte_perm(q2, q3, 0x7632);
            ah[mt][2] = __byte_perm(q4, q5, 0x5410); al[mt][2] = __byte_perm(q4, q5, 0x7632);
            ah[mt][3] = __byte_perm(q6, q7, 0x5410); al[mt][3] = __byte_perm(q6, q7, 0x7632);
        }
        {   // group 1: (Ah + Al) x Bh
            uint32_t b[8][2];
            #pragma unroll
            for (int p = 0; p < 4; p++) {
                uint32_t r[4];
                ldsm4(r, sb + S1_BHI + laneB + p * 16 * RS + ks * 32);
                b[2 * p][0] = r[0]; b[2 * p][1] = r[1];
                b[2 * p + 1][0] = r[2]; b[2 * p + 1][1] = r[3];
            }
            #pragma unroll
            for (int mt = 0; mt < 2; mt++)
                #pragma unroll
                for (int nt = 0; nt < 8; nt++) {
                    mma16816(acc[mt][nt], ah[mt], b[nt]);
                    mma16816(acc[mt][nt], al[mt], b[nt]);
                }
        }
        {   // group 2: Ah x Bl
            uint32_t b[8][2];
            #pragma unroll
            for (int p = 0; p < 4; p++) {
                uint32_t r[4];
                ldsm4(r, sb + S1_BLO + laneB + p * 16 * RS + ks * 32);
                b[2 * p][0] = r[0]; b[2 * p][1] = r[1];
                b[2 * p + 1][0] = r[2]; b[2 * p + 1][1] = r[3];
            }
            #pragma unroll
            for (int mt = 0; mt < 2; mt++)
                #pragma unroll
                for (int nt = 0; nt < 8; nt++)
                    mma16816(acc[mt][nt], ah[mt], b[nt]);
        }
    }

    // epilogue -> g_t[n1][m2][b][r]
    uint2* gt2 = (uint2*)g_t;
    #pragma unroll
    for (int mt = 0; mt < 2; mt++) {
        const size_t rw = (size_t)(row0 + mt * 16);
        #pragma unroll
        for (int nt = 0; nt < 8; nt++) {
            const int cg = nbase + wc * 64 + nt * 8 + qc * 2;   // n = n1*4 + r
            const size_t base = (((size_t)(cg >> 2) * 64 + m2) * 4096) * 4 + (cg & 3);
            gt2[(base + rw * 4) >> 1] =
                make_uint2(fsplit_pack(acc[mt][nt][0]), fsplit_pack(acc[mt][nt][1]));
            gt2[(base + (rw + 8) * 4) >> 1] =
                make_uint2(fsplit_pack(acc[mt][nt][2]), fsplit_pack(acc[mt][nt][3]));
        }
    }
}

// ---------------- stage 2: tile 128(b) x 64(n2), K=256 ----------------------
// SMEM: B tiles only; A fragments direct from g_t (L2-resident slab).
#define S2_BHI 0                    // [chunk][64][RS] per half (9216 B/chunk)
#define S2_BLO 36864
#define S2_SMEM 73728

__global__ void __launch_bounds__(256, 2)
stage2_kernel(float* __restrict__ y, int bslab) {
    extern __shared__ char smem[];
    const uint32_t sb = (uint32_t)__cvta_generic_to_shared(smem);
    const int tid = threadIdx.x, wid = tid >> 5, lane = tid & 31;
    const int n1 = blockIdx.x, b0 = bslab + blockIdx.y * 128;

    {   // B fill (once): chunked [chunk][n2][RS]
        const uint4* bh = g_w2hi + n1 * 2048;
        const uint4* bl = g_w2lo + n1 * 2048;
        #pragma unroll
        for (int i = 0; i < 8; i++) {
            const int idx = tid + 256 * i;
            const int n2 = idx >> 5, w = idx & 31;
            const int chunk = w >> 3, q = w & 7;
            const int dst = chunk * 9216 + n2 * RS + q * 16;
            *(uint4*)(smem + S2_BHI + dst) = bh[idx];
            *(uint4*)(smem + S2_BLO + dst) = bl[idx];
        }
    }
    __syncthreads();   // the only barrier

    const int wr = wid >> 1, wc = wid & 1, qr = lane >> 2, qc = lane & 3;
    const uint32_t laneB = (uint32_t)((wc * 32 + (lane & 7) + ((lane & 16) ? 8 : 0)) * RS +
                                      ((lane & 8) ? 16 : 0));
    const int qch = qc >> 1, rr = (qc & 1) * 2;
    const int row0 = b0 + wr * 32 + qr;

    float acc[2][4][4];
    #pragma unroll
    for (int mt = 0; mt < 2; mt++)
        #pragma unroll
        for (int nt = 0; nt < 4; nt++)
            #pragma unroll
            for (int r = 0; r < 4; r++) acc[mt][nt][r] = 0.f;

    const uint32_t* tb = (const uint32_t*)g_t + (size_t)n1 * 64 * 16384;

    #pragma unroll
    for (int g = 0; g < 16; g++) {                    // g = global k16 index
        const uint32_t* pA = tb + (size_t)(4 * g + qch) * 16384;
        const uint32_t* pB = pA + 2 * 16384;
        uint32_t ah[2][4], al[2][4];
        #pragma unroll
        for (int mt = 0; mt < 2; mt++) {
            const int rw = row0 + mt * 16;
            uint2 x0 = *(const uint2*)(pA + (size_t)rw * 4 + rr);
            uint2 x1 = *(const uint2*)(pA + (size_t)(rw + 8) * 4 + rr);
            uint2 x2 = *(const uint2*)(pB + (size_t)rw * 4 + rr);
            uint2 x3 = *(const uint2*)(pB + (size_t)(rw + 8) * 4 + rr);
            ah[mt][0] = __byte_perm(x0.x, x0.y, 0x5410); al[mt][0] = __byte_perm(x0.x, x0.y, 0x7632);
            ah[mt][1] = __byte_perm(x1.x, x1.y, 0x5410); al[mt][1] = __byte_perm(x1.x, x1.y, 0x7632);
            ah[mt][2] = __byte_perm(x2.x, x2.y, 0x5410); al[mt][2] = __byte_perm(x2.x, x2.y, 0x7632);
            ah[mt][3] = __byte_perm(x3.x, x3.y, 0x5410); al[mt][3] = __byte_perm(x3.x, x3.y, 0x7632);
        }
        const int ch = g >> 2, ksl = g & 3;
        uint32_t bh[4][2], bl[4][2];
        {
            uint32_t r[4];
            ldsm4(r, sb + S2_BHI + ch * 9216 + laneB + ksl * 32);
            bh[0][0] = r[0]; bh[0][1] = r[1]; bh[1][0] = r[2]; bh[1][1] = r[3];
            ldsm4(r, sb + S2_BHI + ch * 9216 + laneB + 16 * RS + ksl * 32);
            bh[2][0] = r[0]; bh[2][1] = r[1]; bh[3][0] = r[2]; bh[3][1] = r[3];
            ldsm4(r, sb + S2_BLO + ch * 9216 + laneB + ksl * 32);
            bl[0][0] = r[0]; bl[0][1] = r[1]; bl[1][0] = r[2]; bl[1][1] = r[3];
            ldsm4(r, sb + S2_BLO + ch * 9216 + laneB + 16 * RS + ksl * 32);
            bl[2][0] = r[0]; bl[2][1] = r[1]; bl[3][0] = r[2]; bl[3][1] = r[3];
        }
        #pragma unroll
        for (int mt = 0; mt < 2; mt++)
            #pragma unroll
            for (int nt = 0; nt < 4; nt++) {
                mma16816(acc[mt][nt], ah[mt], bh[nt]);
                mma16816(acc[mt][nt], al[mt], bh[nt]);
                mma16816(acc[mt][nt], ah[mt], bl[nt]);
            }
    }

    // epilogue: y[b][n1*64 + n2]
    #pragma unroll
    for (int mt = 0; mt < 2; mt++) {
        const size_t rw = (size_t)(row0 + mt * 16);
        #pragma unroll
        for (int nt = 0; nt < 4; nt++) {
            const int col = n1 * 64 + wc * 32 + nt * 8 + qc * 2;
            *(float2*)(y + rw * 4096 + col) = make_float2(acc[mt][nt][0], acc[mt][nt][1]);
            *(float2*)(y + (rw + 8) * 4096 + col) = make_float2(acc[mt][nt][2], acc[mt][nt][3]);
        }
    }
}

// ---------------------------------------------------------------------------
extern "C" void kernel_launch(void* const* d_in, const int* in_sizes, int n_in,
                              void* d_out, int out_size) {
    const float* x  = (const float*)d_in[0];
    const float* W1 = (const float*)d_in[1];
    const float* W2 = (const float*)d_in[2];
    float* y = (float*)d_out;

    cudaFuncSetAttribute(stage1_kernel, cudaFuncAttributeMaxDynamicSharedMemorySize, S1_SMEM);
    cudaFuncSetAttribute(stage2_kernel, cudaFuncAttributeMaxDynamicSharedMemorySize, S2_SMEM);

    prep_w1_kernel<<<64, 256>>>(W1);
    prep_w2_kernel<<<64, 256>>>(W2);
    // Interleave slabs so each slab's t (64MB) is consumed while L2-resident.
    for (int s = 0; s < 4; s++) {
        stage1_kernel<<<dim3(64, SLAB / 128, 2), 256, S1_SMEM>>>(x, s * SLAB);
        stage2_kernel<<<dim3(64, SLAB / 128), 256, S2_SMEM>>>(y, s * SLAB);
    }
}